// round 2
// baseline (speedup 1.0000x reference)
#include <cuda_runtime.h>
#include <math.h>

#define N_NODES 50000
#define N_EDGES 800000
#define N_BATCH 128
#define D_IN    15
#define D_HID   256
#define D_OUT   128
#define LN_EPS  1e-5f

// ---------------- device scratch (static globals; no runtime allocation) ---
__device__ float g_hA[N_NODES * D_HID];        // 51.2 MB
__device__ float g_hB[N_NODES * D_HID];        // 51.2 MB
__device__ float g_xc[N_NODES * 2 * D_HID];    // 102.4 MB  concat [mean | x]
__device__ float g_W [2 * D_HID * D_HID];      // combined [Wl;Wr] (padded)
__device__ int   g_ssrc[N_EDGES];
__device__ int   g_off [N_NODES + 1];
__device__ int   g_cur [N_NODES];
__device__ int   g_deg [N_NODES];
__device__ int   g_bcnt[N_BATCH];

// ---------------- small setup kernels --------------------------------------
__global__ void k_zero(float* out) {
    int i = blockIdx.x * blockDim.x + threadIdx.x;
    if (i < N_NODES) g_deg[i] = 0;
    if (i < N_BATCH) g_bcnt[i] = 0;
    if (i < N_BATCH * D_OUT) out[i] = 0.f;
}

__global__ void k_hist_deg(const int* __restrict__ dst) {
    int e = blockIdx.x * blockDim.x + threadIdx.x;
    if (e < N_EDGES) atomicAdd(&g_deg[dst[e]], 1);
}

__global__ void k_hist_batch(const int* __restrict__ batch) {
    int n = blockIdx.x * blockDim.x + threadIdx.x;
    if (n < N_NODES) atomicAdd(&g_bcnt[batch[n]], 1);
}

// single-block exclusive scan over g_deg -> g_off, g_cur
__global__ void k_scan() {
    __shared__ int wsum[32];
    __shared__ int carry;
    int tid = threadIdx.x, lane = tid & 31, wid = tid >> 5;
    if (tid == 0) carry = 0;
    __syncthreads();
    for (int base = 0; base < N_NODES; base += 1024) {
        int i = base + tid;
        int v = (i < N_NODES) ? g_deg[i] : 0;
        int xv = v;
        #pragma unroll
        for (int o = 1; o < 32; o <<= 1) {
            int t = __shfl_up_sync(0xffffffffu, xv, o);
            if (lane >= o) xv += t;
        }
        if (lane == 31) wsum[wid] = xv;
        __syncthreads();
        if (wid == 0) {
            int y = wsum[lane];
            #pragma unroll
            for (int o = 1; o < 32; o <<= 1) {
                int t = __shfl_up_sync(0xffffffffu, y, o);
                if (lane >= o) y += t;
            }
            wsum[lane] = y;
        }
        __syncthreads();
        int incl = xv + (wid ? wsum[wid - 1] : 0);
        int excl = incl - v + carry;
        if (i < N_NODES) { g_off[i] = excl; g_cur[i] = excl; }
        __syncthreads();
        if (tid == 1023) carry = excl + v;   // old carry + chunk total
        __syncthreads();
    }
    if (tid == 0) g_off[N_NODES] = carry;
}

__global__ void k_scatter(const int* __restrict__ src, const int* __restrict__ dst) {
    int e = blockIdx.x * blockDim.x + threadIdx.x;
    if (e < N_EDGES) {
        int p = atomicAdd(&g_cur[dst[e]], 1);
        g_ssrc[p] = src[e];
    }
}

// combined weight build: rows [0,d)=Wl, [d,2d)=Wr, [2d,kpad)=0
__global__ void k_buildW(const float* __restrict__ Wl, const float* __restrict__ Wr,
                         float* __restrict__ Wc,
                         int d, int ncols, int kpad) {
    int idx = blockIdx.x * blockDim.x + threadIdx.x;
    if (idx >= kpad * ncols) return;
    int k = idx / ncols, n = idx - k * ncols;
    float v = 0.f;
    if (k < d)           v = Wl[k * ncols + n];
    else if (k < 2 * d)  v = Wr[(k - d) * ncols + n];
    Wc[idx] = v;
}

// ---------------- aggregation ---------------------------------------------
// layer 1: d=15, concat row stride 32: [0..14]=mean, [15..29]=x, [30..31]=0
__global__ void k_agg15(const float* __restrict__ x, float* __restrict__ xc) {
    int warp = (blockIdx.x * blockDim.x + threadIdx.x) >> 5;
    if (warp >= N_NODES) return;
    int lane = threadIdx.x & 31;
    int s = g_off[warp], e = g_off[warp + 1];
    float acc = 0.f;
    for (int i = s; i < e; i++) {
        int sn = g_ssrc[i];
        if (lane < D_IN) acc += x[sn * D_IN + lane];
    }
    float inv = 1.f / (float)max(e - s, 1);
    float* row = xc + warp * 32;
    if (lane < D_IN) {
        row[lane] = acc * inv;
        row[D_IN + lane] = x[warp * D_IN + lane];
    }
    if (lane == 15) { row[30] = 0.f; row[31] = 0.f; }
}

// d=256 layers: one warp per node, float4 vectorized; xc row = [mean(256)|x(256)]
__global__ void k_agg256(const float* __restrict__ hin, float* __restrict__ xc) {
    int warp = (blockIdx.x * blockDim.x + threadIdx.x) >> 5;
    if (warp >= N_NODES) return;
    int lane = threadIdx.x & 31;
    int s = g_off[warp], e = g_off[warp + 1];
    float4 a0 = make_float4(0.f, 0.f, 0.f, 0.f);
    float4 a1 = make_float4(0.f, 0.f, 0.f, 0.f);
    const float4* base = (const float4*)hin;
    for (int i = s; i < e; i++) {
        int sn = g_ssrc[i];
        const float4* p = base + sn * 64;
        float4 v0 = p[lane], v1 = p[lane + 32];
        a0.x += v0.x; a0.y += v0.y; a0.z += v0.z; a0.w += v0.w;
        a1.x += v1.x; a1.y += v1.y; a1.z += v1.z; a1.w += v1.w;
    }
    float inv = 1.f / (float)max(e - s, 1);
    a0.x *= inv; a0.y *= inv; a0.z *= inv; a0.w *= inv;
    a1.x *= inv; a1.y *= inv; a1.z *= inv; a1.w *= inv;
    float4* q = (float4*)xc + warp * 128;
    q[lane]      = a0;
    q[lane + 32] = a1;
    const float4* pr = base + warp * 64;
    q[lane + 64] = pr[lane];
    q[lane + 96] = pr[lane + 32];
}

// ---------------- GEMM: out = A(MxK) * W(KxNcols) + bias -------------------
// BM=128, BN=128, BK=16, 256 threads, 8x8 per thread
__global__ __launch_bounds__(256, 2)
void k_gemm(const float* __restrict__ A, int lda, int K,
            const float* __restrict__ W, int ldw,
            const float* __restrict__ bias,
            float* __restrict__ out, int ldo, int M) {
    __shared__ float As[16][132];   // [k][m], padded
    __shared__ float Bs[16][128];   // [k][n]
    int tid = threadIdx.x;
    int tx = tid & 15, ty = tid >> 4;
    int row0 = blockIdx.x * 128;
    int col0 = blockIdx.y * 128;

    float acc[8][8];
    #pragma unroll
    for (int i = 0; i < 8; i++)
        #pragma unroll
        for (int j = 0; j < 8; j++) acc[i][j] = 0.f;

    for (int k0 = 0; k0 < K; k0 += 16) {
        // A tile load (128x16), store transposed
        #pragma unroll
        for (int L = 0; L < 2; L++) {
            int s = tid + L * 256;           // 0..511 float4 slots
            int m = s >> 2;
            int kq = (s & 3) * 4;
            float4 v = make_float4(0.f, 0.f, 0.f, 0.f);
            int gr = row0 + m;
            if (gr < M) v = *(const float4*)&A[gr * lda + k0 + kq];
            As[kq + 0][m] = v.x; As[kq + 1][m] = v.y;
            As[kq + 2][m] = v.z; As[kq + 3][m] = v.w;
        }
        // B tile load (16x128)
        #pragma unroll
        for (int L = 0; L < 2; L++) {
            int s = tid + L * 256;
            int kk = s >> 5;
            int nq = (s & 31) * 4;
            float4 v = *(const float4*)&W[(k0 + kk) * ldw + col0 + nq];
            *(float4*)&Bs[kk][nq] = v;
        }
        __syncthreads();
        #pragma unroll
        for (int kk = 0; kk < 16; kk++) {
            float a[8], b[8];
            *(float4*)(a)     = *(const float4*)&As[kk][ty * 8];
            *(float4*)(a + 4) = *(const float4*)&As[kk][ty * 8 + 4];
            *(float4*)(b)     = *(const float4*)&Bs[kk][tx * 8];
            *(float4*)(b + 4) = *(const float4*)&Bs[kk][tx * 8 + 4];
            #pragma unroll
            for (int i = 0; i < 8; i++)
                #pragma unroll
                for (int j = 0; j < 8; j++)
                    acc[i][j] += a[i] * b[j];
        }
        __syncthreads();
    }

    #pragma unroll
    for (int i = 0; i < 8; i++) {
        int gr = row0 + ty * 8 + i;
        if (gr >= M) continue;
        #pragma unroll
        for (int j = 0; j < 8; j += 4) {
            int gc = col0 + tx * 8 + j;
            float4 o;
            o.x = acc[i][j + 0] + bias[gc + 0];
            o.y = acc[i][j + 1] + bias[gc + 1];
            o.z = acc[i][j + 2] + bias[gc + 2];
            o.w = acc[i][j + 3] + bias[gc + 3];
            *(float4*)&out[gr * ldo + gc] = o;
        }
    }
}

// ---------------- LayerNorm + exact GELU (in-place), warp per row ----------
__global__ void k_ln_gelu(float* __restrict__ h,
                          const float* __restrict__ g, const float* __restrict__ bt,
                          int D) {
    int row = (blockIdx.x * blockDim.x + threadIdx.x) >> 5;
    if (row >= N_NODES) return;
    int lane = threadIdx.x & 31;
    int per = D >> 5;            // 8 (HID) or 4 (OUT)
    float v[8];
    float s = 0.f;
    for (int i = 0; i < per; i++) {
        v[i] = h[row * D + i * 32 + lane];
        s += v[i];
    }
    #pragma unroll
    for (int o = 16; o; o >>= 1) s += __shfl_xor_sync(0xffffffffu, s, o);
    float mu = s / (float)D;
    float var = 0.f;
    for (int i = 0; i < per; i++) {
        float d = v[i] - mu;
        var += d * d;
    }
    #pragma unroll
    for (int o = 16; o; o >>= 1) var += __shfl_xor_sync(0xffffffffu, var, o);
    float rs = rsqrtf(var / (float)D + LN_EPS);
    for (int i = 0; i < per; i++) {
        int c = i * 32 + lane;
        float y = (v[i] - mu) * rs * g[c] + bt[c];
        h[row * D + c] = y * normcdff(y);      // exact gelu: y * Phi(y)
    }
}

// ---------------- final per-batch mean pool --------------------------------
__global__ void k_pool(const float* __restrict__ h, const int* __restrict__ batch,
                       float* __restrict__ out) {
    int warp = (blockIdx.x * blockDim.x + threadIdx.x) >> 5;
    if (warp >= N_NODES) return;
    int lane = threadIdx.x & 31;
    int b = batch[warp];
    #pragma unroll
    for (int i = 0; i < 4; i++)
        atomicAdd(&out[b * D_OUT + i * 32 + lane], h[warp * D_OUT + i * 32 + lane]);
}

__global__ void k_poolfin(float* __restrict__ out) {
    int i = blockIdx.x * blockDim.x + threadIdx.x;
    if (i < N_BATCH * D_OUT) {
        int c = g_bcnt[i / D_OUT];
        out[i] /= (float)max(c, 1);
    }
}

// ---------------- launch ----------------------------------------------------
extern "C" void kernel_launch(void* const* d_in, const int* in_sizes, int n_in,
                              void* d_out, int out_size) {
    const float* x     = (const float*)d_in[0];
    const int*   ei    = (const int*)d_in[1];
    const int*   src   = ei;
    const int*   dst   = ei + N_EDGES;
    const int*   batch = (const int*)d_in[2];
    const float* Wl1 = (const float*)d_in[3],  *Wr1 = (const float*)d_in[4];
    const float* b1  = (const float*)d_in[5],  *g1  = (const float*)d_in[6],  *bt1 = (const float*)d_in[7];
    const float* Wl2 = (const float*)d_in[8],  *Wr2 = (const float*)d_in[9];
    const float* b2  = (const float*)d_in[10], *g2  = (const float*)d_in[11], *bt2 = (const float*)d_in[12];
    const float* Wl3 = (const float*)d_in[13], *Wr3 = (const float*)d_in[14];
    const float* b3  = (const float*)d_in[15], *g3  = (const float*)d_in[16], *bt3 = (const float*)d_in[17];
    const float* Wl4 = (const float*)d_in[18], *Wr4 = (const float*)d_in[19];
    const float* b4  = (const float*)d_in[20], *g4  = (const float*)d_in[21], *bt4 = (const float*)d_in[22];
    float* out = (float*)d_out;

    // device addresses of scratch symbols (host-passed args MUST use these)
    float *hA, *hB, *xc, *Wc;
    cudaGetSymbolAddress((void**)&hA, g_hA);
    cudaGetSymbolAddress((void**)&hB, g_hB);
    cudaGetSymbolAddress((void**)&xc, g_xc);
    cudaGetSymbolAddress((void**)&Wc, g_W);

    const int TB = 256;
    int gridE = (N_EDGES + TB - 1) / TB;
    int gridN = (N_NODES + TB - 1) / TB;
    int gridWarpN = (N_NODES * 32 + TB - 1) / TB;   // warp-per-node kernels

    // ---- setup: degree hist, batch hist, counting sort of edges by dst ----
    k_zero<<<gridN, TB>>>(out);
    k_hist_deg<<<gridE, TB>>>(dst);
    k_hist_batch<<<gridN, TB>>>(batch);
    k_scan<<<1, 1024>>>();
    k_scatter<<<gridE, TB>>>(src, dst);

    dim3 gemmBlk(256);

    // ---- layer 1: K=32 (15 mean + 15 x + 2 pad), N=256 ----
    k_agg15<<<gridWarpN, TB>>>(x, xc);
    k_buildW<<<(32 * D_HID + TB - 1) / TB, TB>>>(Wl1, Wr1, Wc, D_IN, D_HID, 32);
    {
        dim3 grid((N_NODES + 127) / 128, D_HID / 128);
        k_gemm<<<grid, gemmBlk>>>(xc, 32, 32, Wc, D_HID, b1, hA, D_HID, N_NODES);
    }
    k_ln_gelu<<<gridWarpN, TB>>>(hA, g1, bt1, D_HID);

    // ---- layer 2: K=512, N=256 ----
    k_agg256<<<gridWarpN, TB>>>(hA, xc);
    k_buildW<<<(512 * D_HID + TB - 1) / TB, TB>>>(Wl2, Wr2, Wc, D_HID, D_HID, 512);
    {
        dim3 grid((N_NODES + 127) / 128, D_HID / 128);
        k_gemm<<<grid, gemmBlk>>>(xc, 512, 512, Wc, D_HID, b2, hB, D_HID, N_NODES);
    }
    k_ln_gelu<<<gridWarpN, TB>>>(hB, g2, bt2, D_HID);

    // ---- layer 3: K=512, N=256 ----
    k_agg256<<<gridWarpN, TB>>>(hB, xc);
    k_buildW<<<(512 * D_HID + TB - 1) / TB, TB>>>(Wl3, Wr3, Wc, D_HID, D_HID, 512);
    {
        dim3 grid((N_NODES + 127) / 128, D_HID / 128);
        k_gemm<<<grid, gemmBlk>>>(xc, 512, 512, Wc, D_HID, b3, hA, D_HID, N_NODES);
    }
    k_ln_gelu<<<gridWarpN, TB>>>(hA, g3, bt3, D_HID);

    // ---- layer 4: K=512, N=128 ----
    k_agg256<<<gridWarpN, TB>>>(hA, xc);
    k_buildW<<<(512 * D_OUT + TB - 1) / TB, TB>>>(Wl4, Wr4, Wc, D_HID, D_OUT, 512);
    {
        dim3 grid((N_NODES + 127) / 128, D_OUT / 128);
        k_gemm<<<grid, gemmBlk>>>(xc, 512, 512, Wc, D_OUT, b4, hB, D_OUT, N_NODES);
    }
    k_ln_gelu<<<gridWarpN, TB>>>(hB, g4, bt4, D_OUT);

    // ---- per-batch mean pool ----
    k_pool<<<gridWarpN, TB>>>(hB, batch, out);
    k_poolfin<<<(N_BATCH * D_OUT + TB - 1) / TB, TB>>>(out);
}

// round 4
// speedup vs baseline: 1.8973x; 1.8973x over previous
#include <cuda_runtime.h>
#include <cuda_bf16.h>
#include <math.h>
#include <stdint.h>

#define N_NODES 50000
#define N_PAD   50048            // 391 * 128
#define N_EDGES 800000
#define N_BATCH 128
#define D_IN    15
#define D_HID   256
#define D_OUT   128
#define LN_EPS  1e-5f
#define NB_SCAN 49               // ceil(50000/1024)

// ---------------- device scratch -------------------------------------------
__device__ float g_hA[N_PAD * D_HID];                 // 51 MB fp32 activations
__device__ float g_hB[N_PAD * D_HID];                 // 51 MB
__device__ __nv_bfloat16 g_Abf[(size_t)N_PAD * 1024]; // 102 MB  [mean_hi|x_hi|mean_lo|x_lo]
__device__ __nv_bfloat16 g_Wt[256 * 1024];            // W^T bf16: row n, [Wl_hi|Wr_hi|Wl_lo|Wr_lo]
__device__ float g_xc1[N_PAD * 32];                   // layer-1 concat (K=32)
__device__ float g_W1[32 * D_HID];                    // layer-1 fp32 combined W
__device__ int   g_ssrc[N_EDGES];
__device__ int   g_off [N_NODES + 1];
__device__ int   g_cur [N_NODES];
__device__ int   g_deg [N_NODES];
__device__ int   g_bsum[64];
__device__ int   g_bcnt[N_BATCH];

// ---------------- PTX helpers ----------------------------------------------
__device__ __forceinline__ uint32_t smem_to_u32(const void* p) {
    uint32_t a;
    asm("{ .reg .u64 t; cvta.to.shared.u64 t, %1; cvt.u32.u64 %0, t; }" : "=r"(a) : "l"(p));
    return a;
}
#define CP16(dst, src) \
    asm volatile("cp.async.cg.shared.global [%0], [%1], 16;" :: "r"((uint32_t)(dst)), "l"(src) : "memory")
#define CP_COMMIT() asm volatile("cp.async.commit_group;" ::: "memory")
#define CP_WAIT(n)  asm volatile("cp.async.wait_group %0;" :: "n"(n) : "memory")
#define SWZ(b) ((b) ^ (((b) >> 3) & 0x70))
#define LDSM_X4(r0, r1, r2, r3, addr) \
    asm volatile("ldmatrix.sync.aligned.m8n8.x4.shared.b16 {%0,%1,%2,%3}, [%4];" \
                 : "=r"(r0), "=r"(r1), "=r"(r2), "=r"(r3) : "r"(addr))
#define MMA_BF16(d, a, b0, b1) \
    asm volatile("mma.sync.aligned.m16n8k16.row.col.f32.bf16.bf16.f32 " \
                 "{%0,%1,%2,%3}, {%4,%5,%6,%7}, {%8,%9}, {%0,%1,%2,%3};" \
                 : "+f"((d)[0]), "+f"((d)[1]), "+f"((d)[2]), "+f"((d)[3]) \
                 : "r"((a)[0]), "r"((a)[1]), "r"((a)[2]), "r"((a)[3]), \
                   "r"(b0), "r"(b1))

// ---------------- setup kernels --------------------------------------------
__global__ void k_zero(float* out) {
    int i = blockIdx.x * blockDim.x + threadIdx.x;
    if (i < N_NODES) g_deg[i] = 0;
    if (i < N_BATCH) g_bcnt[i] = 0;
    if (i < N_BATCH * D_OUT) out[i] = 0.f;
}
__global__ void k_hist_deg(const int* __restrict__ dst) {
    int e = blockIdx.x * blockDim.x + threadIdx.x;
    if (e < N_EDGES) atomicAdd(&g_deg[dst[e]], 1);
}
__global__ void k_hist_batch(const int* __restrict__ batch) {
    int n = blockIdx.x * blockDim.x + threadIdx.x;
    if (n < N_NODES) atomicAdd(&g_bcnt[batch[n]], 1);
}
// multi-block scan, pass 1: per-block exclusive scan + block totals
__global__ void k_scanA() {
    __shared__ int ws[32];
    int tid = threadIdx.x, lane = tid & 31, wid = tid >> 5;
    int i = blockIdx.x * 1024 + tid;
    int v = (i < N_NODES) ? g_deg[i] : 0;
    int x = v;
    #pragma unroll
    for (int o = 1; o < 32; o <<= 1) {
        int t = __shfl_up_sync(0xffffffffu, x, o);
        if (lane >= o) x += t;
    }
    if (lane == 31) ws[wid] = x;
    __syncthreads();
    if (wid == 0) {
        int y = ws[lane];
        #pragma unroll
        for (int o = 1; o < 32; o <<= 1) {
            int t = __shfl_up_sync(0xffffffffu, y, o);
            if (lane >= o) y += t;
        }
        ws[lane] = y;
    }
    __syncthreads();
    int incl = x + (wid ? ws[wid - 1] : 0);
    if (i < N_NODES) g_off[i] = incl - v;
    if (tid == 1023) g_bsum[blockIdx.x] = incl;
}
__global__ void k_scanB() {
    __shared__ int s[64];
    int tid = threadIdx.x;
    s[tid] = (tid < NB_SCAN) ? g_bsum[tid] : 0;
    __syncthreads();
    if (tid == 0) {
        int acc = 0;
        for (int i = 0; i < NB_SCAN; i++) { int t = s[i]; s[i] = acc; acc += t; }
        g_off[N_NODES] = acc;
    }
    __syncthreads();
    if (tid < NB_SCAN) g_bsum[tid] = s[tid];
}
__global__ void k_scanC() {
    int i = blockIdx.x * 1024 + threadIdx.x;
    if (i < N_NODES) {
        int o = g_off[i] + g_bsum[blockIdx.x];
        g_off[i] = o;
        g_cur[i] = o;
    }
}
__global__ void k_scatter(const int* __restrict__ src, const int* __restrict__ dst) {
    int e = blockIdx.x * blockDim.x + threadIdx.x;
    if (e < N_EDGES) {
        int p = atomicAdd(&g_cur[dst[e]], 1);
        g_ssrc[p] = src[e];
    }
}

// layer-1 combined weight (fp32): rows [0,15)=Wl1, [15,30)=Wr1, [30,32)=0
__global__ void k_buildW1(const float* __restrict__ Wl, const float* __restrict__ Wr) {
    int idx = blockIdx.x * blockDim.x + threadIdx.x;
    if (idx >= 32 * D_HID) return;
    int k = idx / D_HID, n = idx - k * D_HID;
    float v = 0.f;
    if (k < D_IN)          v = Wl[k * D_HID + n];
    else if (k < 2 * D_IN) v = Wr[(k - D_IN) * D_HID + n];
    g_W1[idx] = v;
}

// transposed bf16 hi/lo weight: Wt[n][k], k<256:Wl  256..511:Wr, +512: lo parts
__global__ void k_buildWt(const float* __restrict__ Wl, const float* __restrict__ Wr, int ncols) {
    int idx = blockIdx.x * blockDim.x + threadIdx.x;   // over ncols*512
    if (idx >= ncols * 512) return;
    int n = idx / 512, k = idx - n * 512;
    float v = (k < 256) ? Wl[k * ncols + n] : Wr[(k - 256) * ncols + n];
    __nv_bfloat16 hi = __float2bfloat16(v);
    __nv_bfloat16 lo = __float2bfloat16(v - __bfloat162float(hi));
    g_Wt[n * 1024 + k] = hi;
    g_Wt[n * 1024 + 512 + k] = lo;
}

// ---------------- aggregation ----------------------------------------------
__global__ void k_agg15(const float* __restrict__ x, float* __restrict__ xc) {
    int warp = (blockIdx.x * blockDim.x + threadIdx.x) >> 5;
    if (warp >= N_NODES) return;
    int lane = threadIdx.x & 31;
    int s = g_off[warp], e = g_off[warp + 1];
    float acc = 0.f;
    for (int i = s; i < e; i++) {
        int sn = g_ssrc[i];
        if (lane < D_IN) acc += x[sn * D_IN + lane];
    }
    float inv = 1.f / (float)max(e - s, 1);
    float* row = xc + warp * 32;
    if (lane < D_IN) {
        row[lane] = acc * inv;
        row[D_IN + lane] = x[warp * D_IN + lane];
    }
    if (lane == 15) { row[30] = 0.f; row[31] = 0.f; }
}

__device__ __forceinline__ void split4(float4 v, uint32_t& hi2a, uint32_t& hi2b,
                                       uint32_t& lo2a, uint32_t& lo2b) {
    __nv_bfloat162 h0 = __floats2bfloat162_rn(v.x, v.y);
    __nv_bfloat162 h1 = __floats2bfloat162_rn(v.z, v.w);
    float rx = v.x - __bfloat162float(__low2bfloat16(h0));
    float ry = v.y - __bfloat162float(__high2bfloat16(h0));
    float rz = v.z - __bfloat162float(__low2bfloat16(h1));
    float rw = v.w - __bfloat162float(__high2bfloat16(h1));
    __nv_bfloat162 l0 = __floats2bfloat162_rn(rx, ry);
    __nv_bfloat162 l1 = __floats2bfloat162_rn(rz, rw);
    hi2a = *(uint32_t*)&h0; hi2b = *(uint32_t*)&h1;
    lo2a = *(uint32_t*)&l0; lo2b = *(uint32_t*)&l1;
}

// mean-agg + self, fp32 in -> bf16 hi/lo split out (row = 1024 bf16)
__global__ void k_aggsplit(const float* __restrict__ hin, __nv_bfloat16* __restrict__ Ab) {
    int warp = (blockIdx.x * blockDim.x + threadIdx.x) >> 5;
    if (warp >= N_NODES) return;
    int lane = threadIdx.x & 31;
    int s = g_off[warp], e = g_off[warp + 1];
    float4 a0 = make_float4(0.f, 0.f, 0.f, 0.f);
    float4 a1 = make_float4(0.f, 0.f, 0.f, 0.f);
    const float4* base = (const float4*)hin;
    for (int i = s; i < e; i++) {
        int sn = g_ssrc[i];
        const float4* p = base + sn * 64;
        float4 v0 = p[lane], v1 = p[lane + 32];
        a0.x += v0.x; a0.y += v0.y; a0.z += v0.z; a0.w += v0.w;
        a1.x += v1.x; a1.y += v1.y; a1.z += v1.z; a1.w += v1.w;
    }
    float inv = 1.f / (float)max(e - s, 1);
    a0.x *= inv; a0.y *= inv; a0.z *= inv; a0.w *= inv;
    a1.x *= inv; a1.y *= inv; a1.z *= inv; a1.w *= inv;
    float4 x0 = base[warp * 64 + lane], x1 = base[warp * 64 + lane + 32];

    uint32_t* row = (uint32_t*)(Ab + (size_t)warp * 1024);  // 512 uint32 (bf16x2)
    uint32_t ha, hb, la, lb;
    int c = 2 * lane;
    split4(a0, ha, hb, la, lb);   row[c] = ha;            row[c + 1] = hb;
                                  row[256 + c] = la;      row[256 + c + 1] = lb;
    split4(a1, ha, hb, la, lb);   row[64 + c] = ha;       row[64 + c + 1] = hb;
                                  row[320 + c] = la;      row[320 + c + 1] = lb;
    split4(x0, ha, hb, la, lb);   row[128 + c] = ha;      row[128 + c + 1] = hb;
                                  row[384 + c] = la;      row[384 + c + 1] = lb;
    split4(x1, ha, hb, la, lb);   row[192 + c] = ha;      row[192 + c + 1] = hb;
                                  row[448 + c] = la;      row[448 + c + 1] = lb;
}

// ---------------- layer-1 SIMT GEMM (K=32) ---------------------------------
__global__ __launch_bounds__(256, 2)
void k_gemm1(const float* __restrict__ A, const float* __restrict__ W,
             const float* __restrict__ bias, float* __restrict__ out, int M) {
    __shared__ float As[16][132];
    __shared__ float Bs[16][128];
    int tid = threadIdx.x;
    int tx = tid & 15, ty = tid >> 4;
    int row0 = blockIdx.x * 128;
    int col0 = blockIdx.y * 128;
    float acc[8][8];
    #pragma unroll
    for (int i = 0; i < 8; i++)
        #pragma unroll
        for (int j = 0; j < 8; j++) acc[i][j] = 0.f;
    for (int k0 = 0; k0 < 32; k0 += 16) {
        #pragma unroll
        for (int L = 0; L < 2; L++) {
            int s = tid + L * 256;
            int m = s >> 2;
            int kq = (s & 3) * 4;
            float4 v = make_float4(0.f, 0.f, 0.f, 0.f);
            int gr = row0 + m;
            if (gr < M) v = *(const float4*)&A[gr * 32 + k0 + kq];
            As[kq + 0][m] = v.x; As[kq + 1][m] = v.y;
            As[kq + 2][m] = v.z; As[kq + 3][m] = v.w;
        }
        #pragma unroll
        for (int L = 0; L < 2; L++) {
            int s = tid + L * 256;
            int kk = s >> 5;
            int nq = (s & 31) * 4;
            float4 v = *(const float4*)&W[(k0 + kk) * D_HID + col0 + nq];
            *(float4*)&Bs[kk][nq] = v;
        }
        __syncthreads();
        #pragma unroll
        for (int kk = 0; kk < 16; kk++) {
            float a[8], b[8];
            *(float4*)(a)     = *(const float4*)&As[kk][ty * 8];
            *(float4*)(a + 4) = *(const float4*)&As[kk][ty * 8 + 4];
            *(float4*)(b)     = *(const float4*)&Bs[kk][tx * 8];
            *(float4*)(b + 4) = *(const float4*)&Bs[kk][tx * 8 + 4];
            #pragma unroll
            for (int i = 0; i < 8; i++)
                #pragma unroll
                for (int j = 0; j < 8; j++)
                    acc[i][j] += a[i] * b[j];
        }
        __syncthreads();
    }
    #pragma unroll
    for (int i = 0; i < 8; i++) {
        int gr = row0 + ty * 8 + i;
        if (gr >= M) continue;
        #pragma unroll
        for (int j = 0; j < 8; j += 4) {
            int gc = col0 + tx * 8 + j;
            float4 o;
            o.x = acc[i][j + 0] + bias[gc + 0];
            o.y = acc[i][j + 1] + bias[gc + 1];
            o.z = acc[i][j + 2] + bias[gc + 2];
            o.w = acc[i][j + 3] + bias[gc + 3];
            *(float4*)&out[gr * D_HID + gc] = o;
        }
    }
}

// ---------------- mma.sync bf16 split GEMM ----------------------------------
// out(M x Ncols) = A(stored hi/lo bf16, row=1024) @ W + bias
// 24 chunks of K=64: c0-7: A_hi*W_hi, c8-15: A_lo*W_hi, c16-23: A_hi*W_lo
// BM=128, BN=128, 256 threads, 8 warps (4m x 2n), warp tile 32x64
__global__ __launch_bounds__(256)
void k_gemm_mma(const __nv_bfloat16* __restrict__ A, const __nv_bfloat16* __restrict__ Wt,
                const float* __restrict__ bias, float* __restrict__ out,
                int Ncols, int M) {
    extern __shared__ char smem[];
    uint32_t sb = smem_to_u32(smem);
    const int STAGE = 32768;        // 16KB A + 16KB B
    int tid = threadIdx.x, lane = tid & 31, warp = tid >> 5;
    int warp_m = warp & 3, warp_n = warp >> 2;
    int row0 = blockIdx.x * 128, col0 = blockIdx.y * 128;

    float acc[2][8][4];
    #pragma unroll
    for (int mi = 0; mi < 2; mi++)
        #pragma unroll
        for (int nb = 0; nb < 8; nb++)
            #pragma unroll
            for (int r = 0; r < 4; r++) acc[mi][nb][r] = 0.f;

    auto issue = [&](int c, int s) {
        int kA = ((c < 16) ? c : c - 16) * 64;
        int kB = ((c < 8) ? c : c - 8) * 64;
        uint32_t dA = sb + s * STAGE;
        uint32_t dB = dA + 16384;
        const __nv_bfloat16* pa = A + (size_t)row0 * 1024 + kA;
        const __nv_bfloat16* pb = Wt + (size_t)col0 * 1024 + kB;
        #pragma unroll
        for (int i = 0; i < 4; i++) {
            int t = tid + i * 256;
            int r = t >> 3, seg = t & 7;
            CP16(dA + SWZ(r * 128 + seg * 16), pa + (size_t)r * 1024 + seg * 8);
        }
        #pragma unroll
        for (int i = 0; i < 4; i++) {
            int t = tid + i * 256;
            int r = t >> 3, seg = t & 7;
            CP16(dB + SWZ(r * 128 + seg * 16), pb + (size_t)r * 1024 + seg * 8);
        }
        CP_COMMIT();
    };

    issue(0, 0);
    for (int c = 0; c < 24; c++) {
        int s = c & 1;
        if (c < 23) { issue(c + 1, s ^ 1); CP_WAIT(1); }
        else        { CP_WAIT(0); }
        __syncthreads();
        uint32_t sA = sb + s * STAGE, sB = sA + 16384;
        #pragma unroll
        for (int kk = 0; kk < 64; kk += 16) {
            uint32_t a[2][4], b[4][4];
            #pragma unroll
            for (int mi = 0; mi < 2; mi++) {
                int r = warp_m * 32 + mi * 16 + (lane & 15);
                int cb = (kk + (lane >> 4) * 8) * 2;
                LDSM_X4(a[mi][0], a[mi][1], a[mi][2], a[mi][3], sA + SWZ(r * 128 + cb));
            }
            #pragma unroll
            for (int nb4 = 0; nb4 < 4; nb4++) {
                int g = lane >> 3;
                int n = warp_n * 64 + nb4 * 16 + (lane & 7) + (g >> 1) * 8;
                int kb = (kk + (g & 1) * 8) * 2;
                LDSM_X4(b[nb4][0], b[nb4][1], b[nb4][2], b[nb4][3], sB + SWZ(n * 128 + kb));
            }
            #pragma unroll
            for (int mi = 0; mi < 2; mi++)
                #pragma unroll
                for (int nb = 0; nb < 8; nb++) {
                    uint32_t b0 = b[nb >> 1][(nb & 1) * 2];
                    uint32_t b1 = b[nb >> 1][(nb & 1) * 2 + 1];
                    MMA_BF16(acc[mi][nb], a[mi], b0, b1);
                }
        }
        __syncthreads();
    }

    // epilogue: d0,d1 -> (row, col), (row, col+1); d2,d3 -> row+8
    int tr = lane >> 2, tc = lane & 3;
    #pragma unroll
    for (int mi = 0; mi < 2; mi++) {
        #pragma unroll
        for (int nb = 0; nb < 8; nb++) {
            int rg = row0 + warp_m * 32 + mi * 16 + tr;
            int cg = col0 + warp_n * 64 + nb * 8 + tc * 2;
            float bx = bias[cg], by = bias[cg + 1];
            if (rg < M) {
                float2 o = make_float2(acc[mi][nb][0] + bx, acc[mi][nb][1] + by);
                *(float2*)&out[(size_t)rg * Ncols + cg] = o;
            }
            if (rg + 8 < M) {
                float2 o = make_float2(acc[mi][nb][2] + bx, acc[mi][nb][3] + by);
                *(float2*)&out[(size_t)(rg + 8) * Ncols + cg] = o;
            }
        }
    }
}

// ---------------- LayerNorm + exact GELU ------------------------------------
__global__ void k_ln_gelu(float* __restrict__ h, const float* __restrict__ g,
                          const float* __restrict__ bt, int D) {
    int row = (blockIdx.x * blockDim.x + threadIdx.x) >> 5;
    if (row >= N_NODES) return;
    int lane = threadIdx.x & 31;
    int per = D >> 5;
    float v[8];
    float s = 0.f;
    for (int i = 0; i < per; i++) {
        v[i] = h[row * D + i * 32 + lane];
        s += v[i];
    }
    #pragma unroll
    for (int o = 16; o; o >>= 1) s += __shfl_xor_sync(0xffffffffu, s, o);
    float mu = s / (float)D;
    float var = 0.f;
    for (int i = 0; i < per; i++) { float d = v[i] - mu; var += d * d; }
    #pragma unroll
    for (int o = 16; o; o >>= 1) var += __shfl_xor_sync(0xffffffffu, var, o);
    float rs = rsqrtf(var / (float)D + LN_EPS);
    for (int i = 0; i < per; i++) {
        int c = i * 32 + lane;
        float y = (v[i] - mu) * rs * g[c] + bt[c];
        h[row * D + c] = y * normcdff(y);
    }
}

// ---------------- final per-batch mean pool ---------------------------------
__global__ void k_pool(const float* __restrict__ h, const int* __restrict__ batch,
                       float* __restrict__ out) {
    int warp = (blockIdx.x * blockDim.x + threadIdx.x) >> 5;
    if (warp >= N_NODES) return;
    int lane = threadIdx.x & 31;
    int b = batch[warp];
    #pragma unroll
    for (int i = 0; i < 4; i++)
        atomicAdd(&out[b * D_OUT + i * 32 + lane], h[warp * D_OUT + i * 32 + lane]);
}
__global__ void k_poolfin(float* __restrict__ out) {
    int i = blockIdx.x * blockDim.x + threadIdx.x;
    if (i < N_BATCH * D_OUT) {
        int c = g_bcnt[i / D_OUT];
        out[i] /= (float)max(c, 1);
    }
}

// ---------------- launch -----------------------------------------------------
extern "C" void kernel_launch(void* const* d_in, const int* in_sizes, int n_in,
                              void* d_out, int out_size) {
    const float* x     = (const float*)d_in[0];
    const int*   ei    = (const int*)d_in[1];
    const int*   src   = ei;
    const int*   dst   = ei + N_EDGES;
    const int*   batch = (const int*)d_in[2];
    const float* Wl1 = (const float*)d_in[3],  *Wr1 = (const float*)d_in[4];
    const float* b1  = (const float*)d_in[5],  *g1  = (const float*)d_in[6],  *bt1 = (const float*)d_in[7];
    const float* Wl2 = (const float*)d_in[8],  *Wr2 = (const float*)d_in[9];
    const float* b2  = (const float*)d_in[10], *g2  = (const float*)d_in[11], *bt2 = (const float*)d_in[12];
    const float* Wl3 = (const float*)d_in[13], *Wr3 = (const float*)d_in[14];
    const float* b3  = (const float*)d_in[15], *g3  = (const float*)d_in[16], *bt3 = (const float*)d_in[17];
    const float* Wl4 = (const float*)d_in[18], *Wr4 = (const float*)d_in[19];
    const float* b4  = (const float*)d_in[20], *g4  = (const float*)d_in[21], *bt4 = (const float*)d_in[22];
    float* out = (float*)d_out;

    float *hA, *hB, *xc1, *W1;
    __nv_bfloat16 *Abf, *Wt;
    cudaGetSymbolAddress((void**)&hA,  g_hA);
    cudaGetSymbolAddress((void**)&hB,  g_hB);
    cudaGetSymbolAddress((void**)&xc1, g_xc1);
    cudaGetSymbolAddress((void**)&W1,  g_W1);
    cudaGetSymbolAddress((void**)&Abf, g_Abf);
    cudaGetSymbolAddress((void**)&Wt,  g_Wt);

    const int TB = 256;
    int gridE = (N_EDGES + TB - 1) / TB;
    int gridN = (N_NODES + TB - 1) / TB;
    int gridWarpN = (N_NODES * 32 + TB - 1) / TB;
    int gridTiles = N_PAD / 128;   // 391

    const int SMEM_MMA = 2 * 32768;  // 64 KB double-buffered
    cudaFuncSetAttribute(k_gemm_mma, cudaFuncAttributeMaxDynamicSharedMemorySize, SMEM_MMA);

    // ---- setup ----
    k_zero<<<gridN, TB>>>(out);
    k_hist_deg<<<gridE, TB>>>(dst);
    k_hist_batch<<<gridN, TB>>>(batch);
    k_scanA<<<NB_SCAN, 1024>>>();
    k_scanB<<<1, 64>>>();
    k_scanC<<<NB_SCAN, 1024>>>();
    k_scatter<<<gridE, TB>>>(src, dst);

    // ---- layer 1: SIMT, K=32 ----
    k_agg15<<<gridWarpN, TB>>>(x, xc1);
    k_buildW1<<<(32 * D_HID + TB - 1) / TB, TB>>>(Wl1, Wr1);
    {
        dim3 grid(gridTiles, D_HID / 128);
        k_gemm1<<<grid, 256>>>(xc1, W1, b1, hA, N_NODES);
    }
    k_ln_gelu<<<gridWarpN, TB>>>(hA, g1, bt1, D_HID);

    // ---- layer 2 ----
    k_aggsplit<<<gridWarpN, TB>>>(hA, Abf);
    k_buildWt<<<(D_HID * 512 + TB - 1) / TB, TB>>>(Wl2, Wr2, D_HID);
    {
        dim3 grid(gridTiles, 2);
        k_gemm_mma<<<grid, 256, SMEM_MMA>>>(Abf, Wt, b2, hB, 256, N_NODES);
    }
    k_ln_gelu<<<gridWarpN, TB>>>(hB, g2, bt2, D_HID);

    // ---- layer 3 ----
    k_aggsplit<<<gridWarpN, TB>>>(hB, Abf);
    k_buildWt<<<(D_HID * 512 + TB - 1) / TB, TB>>>(Wl3, Wr3, D_HID);
    {
        dim3 grid(gridTiles, 2);
        k_gemm_mma<<<grid, 256, SMEM_MMA>>>(Abf, Wt, b3, hA, 256, N_NODES);
    }
    k_ln_gelu<<<gridWarpN, TB>>>(hA, g3, bt3, D_HID);

    // ---- layer 4 (N=128) ----
    k_aggsplit<<<gridWarpN, TB>>>(hA, Abf);
    k_buildWt<<<(D_OUT * 512 + TB - 1) / TB, TB>>>(Wl4, Wr4, D_OUT);
    {
        dim3 grid(gridTiles, 1);
        k_gemm_mma<<<grid, 256, SMEM_MMA>>>(Abf, Wt, b4, hB, 128, N_NODES);
    }
    k_ln_gelu<<<gridWarpN, TB>>>(hB, g4, bt4, D_OUT);

    // ---- pool ----
    k_pool<<<gridWarpN, TB>>>(hB, batch, out);
    k_poolfin<<<(N_BATCH * D_OUT + TB - 1) / TB, TB>>>(out);
}